// round 1
// baseline (speedup 1.0000x reference)
#include <cuda_runtime.h>

#define NN 10000
#define KK 16
#define CH 20      // padded ext channels: 16 Yn + s + 3 pad (80B rows, 16B aligned)
#define SI 128     // rows per smem stage
#define JG 512     // j columns per CTA (2 per thread * 256 threads)
#define IB 715     // rows per i-group
#define NJ 20      // ceil(10000/512)
#define NI 14      // ceil(10000/715)

__device__ float g_gamma[KK];
__device__ float g_colsum[KK];
__device__ float g_result;
__device__ float g_ext[(size_t)NN * CH];   // 800 KB scratch (device global: allowed)

typedef unsigned long long u64;

__device__ __forceinline__ u64 pack2(float x, float y) {
    u64 r; asm("mov.b64 %0, {%1, %2};" : "=l"(r) : "f"(x), "f"(y)); return r;
}
__device__ __forceinline__ void unpack2(u64 v, float& x, float& y) {
    asm("mov.b64 {%0, %1}, %2;" : "=f"(x), "=f"(y) : "l"(v));
}
__device__ __forceinline__ void fma2(u64& d, u64 a, u64 b) {
    // packed f32x2 FMA (sm_100+): d = a*b + d on both 32-bit halves
    asm("fma.rn.f32x2 %0, %1, %2, %0;" : "+l"(d) : "l"(a), "l"(b));
}
__device__ __forceinline__ void cp16(unsigned dst, const void* src) {
    asm volatile("cp.async.cg.shared.global [%0], [%1], 16;" :: "r"(dst), "l"(src) : "memory");
}

// ---------------------------------------------------------------------------
__global__ void k_zero() {
    int t = threadIdx.x;
    if (t < KK) { g_gamma[t] = 0.f; g_colsum[t] = 0.f; }
    if (t == 0) g_result = 0.f;
}

// gamma[k] = sum_i Y[i,k]*deg[i]; colsum[k] = sum_i Y[i,k]
__global__ void k_gamma(const float* __restrict__ Y, const float* __restrict__ deg) {
    int i = blockIdx.x * blockDim.x + threadIdx.x;
    float y[KK];
    float d = 0.f;
    if (i < NN) {
        d = deg[i];
        const float4* y4 = (const float4*)(Y + (size_t)i * KK);
#pragma unroll
        for (int q = 0; q < 4; q++) {
            float4 v = y4[q];
            y[4*q+0] = v.x; y[4*q+1] = v.y; y[4*q+2] = v.z; y[4*q+3] = v.w;
        }
    } else {
#pragma unroll
        for (int k = 0; k < KK; k++) y[k] = 0.f;
    }
    __shared__ float sg[KK], sc[KK];
    if (threadIdx.x < KK) { sg[threadIdx.x] = 0.f; sc[threadIdx.x] = 0.f; }
    __syncthreads();
#pragma unroll
    for (int k = 0; k < KK; k++) {
        float gv = y[k] * d, cv = y[k];
#pragma unroll
        for (int o = 16; o; o >>= 1) {
            gv += __shfl_xor_sync(0xffffffffu, gv, o);
            cv += __shfl_xor_sync(0xffffffffu, cv, o);
        }
        if ((threadIdx.x & 31) == 0) { atomicAdd(&sg[k], gv); atomicAdd(&sc[k], cv); }
    }
    __syncthreads();
    if (threadIdx.x < KK) {
        atomicAdd(&g_gamma[threadIdx.x], sg[threadIdx.x]);
        atomicAdd(&g_colsum[threadIdx.x], sc[threadIdx.x]);
    }
}

// ext[i] = [ Y[i,k]/gamma[k] (k<16), s_i, 0, 0, 0 ]
__global__ void k_ext(const float* __restrict__ Y) {
    int i = blockIdx.x * blockDim.x + threadIdx.x;
    if (i >= NN) return;
    float inv[KK];
#pragma unroll
    for (int k = 0; k < KK; k++) inv[k] = 1.0f / g_gamma[k];
    const float4* y4 = (const float4*)(Y + (size_t)i * KK);
    float e[CH];
    float s = 0.f;
#pragma unroll
    for (int q = 0; q < 4; q++) {
        float4 v = y4[q];
        e[4*q+0] = v.x * inv[4*q+0]; s += e[4*q+0];
        e[4*q+1] = v.y * inv[4*q+1]; s += e[4*q+1];
        e[4*q+2] = v.z * inv[4*q+2]; s += e[4*q+2];
        e[4*q+3] = v.w * inv[4*q+3]; s += e[4*q+3];
    }
    e[16] = s; e[17] = 0.f; e[18] = 0.f; e[19] = 0.f;
    float4* dst = (float4*)(g_ext + (size_t)i * CH);
#pragma unroll
    for (int q = 0; q < 5; q++)
        dst[q] = make_float4(e[4*q+0], e[4*q+1], e[4*q+2], e[4*q+3]);
}

// ---------------------------------------------------------------------------
// Main: u[j, 0:18] = sum_i A[i,j] * ext[i, 0:18]  (u in registers, 2 j per thread)
// then error_cut partial = sum_j ( u[j,16] - sum_k u[j,k]*Y[j,k] )
__global__ void __launch_bounds__(256, 2) k_main(const float* __restrict__ A,
                                                 const float* __restrict__ Y) {
    __shared__ float smE[2][SI * CH];   // 2 x 10240 B double buffer

    const int t   = threadIdx.x;
    const int jt  = blockIdx.x * JG + 2 * t;   // this thread's two j's: jt, jt+1
    const bool jv = (jt < NN);                 // boundary is even, both valid or neither
    const int i0   = blockIdx.y * IB;
    const int iend = min(NN, i0 + IB);
    const int nst  = (iend - i0 + SI - 1) / SI;

    u64 acc0[9], acc1[9];
#pragma unroll
    for (int p = 0; p < 9; p++) { acc0[p] = 0ull; acc1[p] = 0ull; }

    // zero both buffers so tail rows of a partial stage multiply as 0.0 (avoid NaN*0)
    {
        float4* z = (float4*)&smE[0][0];
        for (int c = t; c < 2 * SI * CH / 4; c += 256) z[c] = make_float4(0.f, 0.f, 0.f, 0.f);
    }
    __syncthreads();

    // stage 0 async copy
    {
        int rc = min(SI, iend - i0);
        int chunks = rc * (CH / 4);
        const char* src = (const char*)(g_ext + (size_t)i0 * CH);
        unsigned dstb = (unsigned)__cvta_generic_to_shared(&smE[0][0]);
        for (int c = t; c < chunks; c += 256) cp16(dstb + c * 16, src + c * 16);
        asm volatile("cp.async.commit_group;" ::: "memory");
    }

    int buf = 0;
    for (int s = 0; s < nst; s++) {
        if (s + 1 < nst) {
            int rb = i0 + (s + 1) * SI;
            int rc = min(SI, iend - rb);
            int chunks = rc * (CH / 4);
            const char* src = (const char*)(g_ext + (size_t)rb * CH);
            unsigned dstb = (unsigned)__cvta_generic_to_shared(&smE[buf ^ 1][0]);
            for (int c = t; c < chunks; c += 256) cp16(dstb + c * 16, src + c * 16);
            asm volatile("cp.async.commit_group;" ::: "memory");
            asm volatile("cp.async.wait_group 1;" ::: "memory");
        } else {
            asm volatile("cp.async.wait_group 0;" ::: "memory");
        }
        __syncthreads();

        const int rb = i0 + s * SI;
        const int rcount = min(SI, iend - rb);
        const float* Abase = A + (size_t)rb * NN + jt;
        const float* eb = &smE[buf][0];

        // software-pipelined: prefetch A for the next 4-row group
        float2 a[4];
#pragma unroll
        for (int q = 0; q < 4; q++) {
            a[q] = make_float2(0.f, 0.f);
            if (jv && q < rcount) a[q] = *(const float2*)(Abase + (size_t)q * NN);
        }
        for (int rr = 0; rr < rcount; rr += 4) {
            float2 b[4];
#pragma unroll
            for (int q = 0; q < 4; q++) {
                int r = rr + 4 + q;
                b[q] = make_float2(0.f, 0.f);
                if (jv && r < rcount) b[q] = *(const float2*)(Abase + (size_t)r * NN);
            }
#pragma unroll
            for (int q = 0; q < 4; q++) {
                const float* er = eb + (rr + q) * CH;   // rr+q <= 127: in-bounds, zeroed tail
                u64 ax = pack2(a[q].x, a[q].x);
                u64 ay = pack2(a[q].y, a[q].y);
#pragma unroll
                for (int p = 0; p < 9; p++) {
                    u64 yp = *(const u64*)(er + 2 * p);  // LDS.64 broadcast
                    fma2(acc0[p], ax, yp);
                    fma2(acc1[p], ay, yp);
                }
            }
#pragma unroll
            for (int q = 0; q < 4; q++) a[q] = b[q];
        }
        __syncthreads();
        buf ^= 1;
    }

    // epilogue: e_j = u[j,16] - sum_k u[j,k] * Y[j,k]
    float part = 0.f;
    if (jv) {
#pragma unroll
        for (int m = 0; m < 2; m++) {
            const u64* acc = (m == 0) ? acc0 : acc1;
            const float4* yj = (const float4*)(Y + (size_t)(jt + m) * KK);
            float lo, hi;
            unpack2(acc[8], lo, hi);
            float e = lo;                          // channel 16 = sum_i A_ij * s_i
#pragma unroll
            for (int q = 0; q < 4; q++) {
                float4 yv = yj[q];
                unpack2(acc[2*q + 0], lo, hi);
                e -= lo * yv.x + hi * yv.y;
                unpack2(acc[2*q + 1], lo, hi);
                e -= lo * yv.z + hi * yv.w;
            }
            part += e;
        }
    }
#pragma unroll
    for (int o = 16; o; o >>= 1) part += __shfl_xor_sync(0xffffffffu, part, o);
    if ((t & 31) == 0) atomicAdd(&g_result, part);
}

// ---------------------------------------------------------------------------
__global__ void k_final(float* out) {
    int t = threadIdx.x;
    float v = 0.f;
    if (t < KK) { float c = g_colsum[t] - 625.0f; v = c * c; }
#pragma unroll
    for (int o = 16; o; o >>= 1) v += __shfl_xor_sync(0xffffffffu, v, o);
    if (t == 0) out[0] = g_result + v;
}

// ---------------------------------------------------------------------------
extern "C" void kernel_launch(void* const* d_in, const int* in_sizes, int n_in,
                              void* d_out, int out_size) {
    const float* Y = nullptr;
    const float* A = nullptr;
    const float* deg = nullptr;
    for (int i = 0; i < n_in; i++) {
        if (in_sizes[i] == NN * NN)       A = (const float*)d_in[i];
        else if (in_sizes[i] == NN * KK)  Y = (const float*)d_in[i];
        else if (in_sizes[i] == NN)       deg = (const float*)d_in[i];
    }
    if (!Y)   Y = (const float*)d_in[0];
    if (!A)   A = (const float*)d_in[1];
    if (!deg) deg = (const float*)d_in[2];

    k_zero<<<1, 64>>>();
    k_gamma<<<40, 256>>>(Y, deg);
    k_ext<<<40, 256>>>(Y);
    dim3 grid(NJ, NI);
    k_main<<<grid, 256>>>(A, Y);
    k_final<<<1, 32>>>((float*)d_out);
}

// round 3
// speedup vs baseline: 1.4277x; 1.4277x over previous
#include <cuda_runtime.h>
#include <cstdint>

#define NN 10000
#define KK 16
#define MT 128              // i rows per CTA (8 warps x 16)
#define JC 64               // j per pipeline stage
#define DEPTH 3
#define NIT 79              // ceil(10000/128)
#define NJG 8               // j groups: 7 x 1280 + 1 x 1040
#define BT_LD 10048         // padded (1-Y)^T leading dim (>= 8960+17*64)
#define SLOT_BYTES 36864    // 32KB A + 4KB B
#define MEAN_NODES 625.0f

__device__ float g_gamma[KK];
__device__ float g_colsum[KK];
__device__ float g_result;
__device__ float g_bt[KK * BT_LD];   // (1-Y)^T, k-major, zero padded beyond j=NN

// ---------------------------------------------------------------- helpers
__device__ __forceinline__ void cp16(unsigned dst, const void* src) {
    asm volatile("cp.async.cg.shared.global [%0], [%1], 16;" :: "r"(dst), "l"(src) : "memory");
}
__device__ __forceinline__ void zero16(unsigned dst) {
    asm volatile("st.shared.v4.b32 [%0], {%1,%1,%1,%1};" :: "r"(dst), "r"(0) : "memory");
}
__device__ __forceinline__ void ldsm4(uint32_t& r0, uint32_t& r1, uint32_t& r2, uint32_t& r3,
                                      unsigned addr) {
    asm volatile("ldmatrix.sync.aligned.m8n8.x4.shared.b16 {%0,%1,%2,%3}, [%4];"
                 : "=r"(r0), "=r"(r1), "=r"(r2), "=r"(r3) : "r"(addr));
}
__device__ __forceinline__ void mma_tf32(float* d, const uint32_t* a, uint32_t b0, uint32_t b1) {
    asm volatile(
        "mma.sync.aligned.m16n8k8.row.col.f32.tf32.tf32.f32 "
        "{%0,%1,%2,%3}, {%4,%5,%6,%7}, {%8,%9}, {%0,%1,%2,%3};"
        : "+f"(d[0]), "+f"(d[1]), "+f"(d[2]), "+f"(d[3])
        : "r"(a[0]), "r"(a[1]), "r"(a[2]), "r"(a[3]), "r"(b0), "r"(b1));
}

// ---------------------------------------------------------------- prep kernels
__global__ void k_zero() {
    int t = threadIdx.x;
    if (t < KK) { g_gamma[t] = 0.f; g_colsum[t] = 0.f; }
    if (t == 0) g_result = 0.f;
}

__global__ void k_gamma(const float* __restrict__ Y, const float* __restrict__ deg) {
    int i = blockIdx.x * blockDim.x + threadIdx.x;
    float y[KK];
    float d = 0.f;
    if (i < NN) {
        d = deg[i];
        const float4* y4 = (const float4*)(Y + (size_t)i * KK);
#pragma unroll
        for (int q = 0; q < 4; q++) {
            float4 v = y4[q];
            y[4*q+0] = v.x; y[4*q+1] = v.y; y[4*q+2] = v.z; y[4*q+3] = v.w;
        }
    } else {
#pragma unroll
        for (int k = 0; k < KK; k++) y[k] = 0.f;
    }
    __shared__ float sg[KK], sc[KK];
    if (threadIdx.x < KK) { sg[threadIdx.x] = 0.f; sc[threadIdx.x] = 0.f; }
    __syncthreads();
#pragma unroll
    for (int k = 0; k < KK; k++) {
        float gv = y[k] * d, cv = y[k];
#pragma unroll
        for (int o = 16; o; o >>= 1) {
            gv += __shfl_xor_sync(0xffffffffu, gv, o);
            cv += __shfl_xor_sync(0xffffffffu, cv, o);
        }
        if ((threadIdx.x & 31) == 0) { atomicAdd(&sg[k], gv); atomicAdd(&sc[k], cv); }
    }
    __syncthreads();
    if (threadIdx.x < KK) {
        atomicAdd(&g_gamma[threadIdx.x], sg[threadIdx.x]);
        atomicAdd(&g_colsum[threadIdx.x], sc[threadIdx.x]);
    }
}

// g_bt[k][j] = 1 - Y[j][k] for j < NN, else 0
__global__ void k_bt(const float* __restrict__ Y) {
    int j = blockIdx.x * blockDim.x + threadIdx.x;
    if (j >= BT_LD) return;
    if (j < NN) {
        const float4* y4 = (const float4*)(Y + (size_t)j * KK);
#pragma unroll
        for (int q = 0; q < 4; q++) {
            float4 v = y4[q];
            g_bt[(4*q+0) * BT_LD + j] = 1.0f - v.x;
            g_bt[(4*q+1) * BT_LD + j] = 1.0f - v.y;
            g_bt[(4*q+2) * BT_LD + j] = 1.0f - v.z;
            g_bt[(4*q+3) * BT_LD + j] = 1.0f - v.w;
        }
    } else {
#pragma unroll
        for (int k = 0; k < KK; k++) g_bt[k * BT_LD + j] = 0.f;
    }
}

// ---------------------------------------------------------------- main
extern __shared__ char dsm[];

__global__ void __launch_bounds__(256, 2) k_main(const float* __restrict__ A,
                                                 const float* __restrict__ Y) {
    __shared__ float s_red;

    const int tid  = threadIdx.x;
    const int w    = tid >> 5;
    const int lane = tid & 31;

    const unsigned smBase = (unsigned)__cvta_generic_to_shared(dsm);

    const int it = blockIdx.x;
    const int g  = blockIdx.y;
    const int i0 = it * MT;
    const int j_begin = g * 1280;
    const int nst = (g < 7) ? 20 : 17;   // 7*1280 + 1040 = 10000 (+pad to 1088)

    // ---- per-thread ldmatrix source rows (within warp) ----
    const int m    = lane >> 3;      // matrix index 0..3
    const int rsub = lane & 7;
    // A: matrices {0,1} = rows r0..+7 / r0+8..+15 at chunk parity 0; {2,3} same rows parity 1
    const int rA   = w * 16 + ((m & 1) << 3) + rsub;
    const int pA   = m >> 1;
    const unsigned aOffBase = (unsigned)(rA * 256);
    const unsigned aXor     = (unsigned)((rA & 7) * 16);
    // B: matrices {0,1} = rows 0..7 parity {0,1}; {2,3} = rows 8..15 parity {0,1}
    const int rB   = ((m >> 1) << 3) + rsub;
    const int pB   = m & 1;
    const unsigned bOffBase = 32768u + (unsigned)(rB * 256);
    const unsigned bXor     = (unsigned)((rB & 7) * 16);

    float acc0[4] = {0.f, 0.f, 0.f, 0.f};   // k channels 0..7
    float acc1[4] = {0.f, 0.f, 0.f, 0.f};   // k channels 8..15

    // ---- stage filler ----
    auto fill = [&](int s) {
        const unsigned sm = smBase + (unsigned)((s % DEPTH) * SLOT_BYTES);
        const int j0 = j_begin + s * JC;
        // A: 128 rows x 16 chunks of 16B
#pragma unroll
        for (int c = tid; c < 2048; c += 256) {
            int r = c >> 4, u = c & 15;
            unsigned dst = sm + (unsigned)(r * 256) + (unsigned)((u ^ (r & 7)) * 16);
            int i = i0 + r;
            int jc = j0 + u * 4;
            if (i < NN && jc < NN)
                cp16(dst, (const char*)(A + (size_t)i * NN + jc));
            else
                zero16(dst);
        }
        // B: 16 rows x 16 chunks = 256, one per thread (always in padded scratch)
        {
            int r = tid >> 4, u = tid & 15;
            unsigned dst = sm + 32768u + (unsigned)(r * 256) + (unsigned)((u ^ (r & 7)) * 16);
            cp16(dst, (const char*)(g_bt + (size_t)r * BT_LD + j0 + u * 4));
        }
        asm volatile("cp.async.commit_group;" ::: "memory");
    };

    // prologue
    fill(0); fill(1); fill(2);

    for (int s = 0; s < nst; s++) {
        asm volatile("cp.async.wait_group 2;" ::: "memory");
        __syncthreads();

        const unsigned sm = smBase + (unsigned)((s % DEPTH) * SLOT_BYTES);
#pragma unroll
        for (int kk = 0; kk < 8; kk++) {
            uint32_t a[4], b[4];
            unsigned aAddr = sm + aOffBase + ((unsigned)((2 * kk + pA) * 16) ^ aXor);
            unsigned bAddr = sm + bOffBase + ((unsigned)((2 * kk + pB) * 16) ^ bXor);
            ldsm4(a[0], a[1], a[2], a[3], aAddr);
            ldsm4(b[0], b[1], b[2], b[3], bAddr);
            mma_tf32(acc0, a, b[0], b[1]);
            mma_tf32(acc1, a, b[2], b[3]);
        }
        __syncthreads();

        if (s + DEPTH < nst) fill(s + DEPTH);
        else asm volatile("cp.async.commit_group;" ::: "memory");
    }

    // ---- epilogue: part = sum over this thread's D elems of D * Y[i][k]/gamma[k] ----
    const int q  = lane & 3;
    const int rAi = i0 + w * 16 + (lane >> 2);
    const int rBi = rAi + 8;
    float part = 0.f;
    if (rAi < NN) {
        const float* yr = Y + (size_t)rAi * KK;
        part += acc0[0] * yr[2*q]     / g_gamma[2*q];
        part += acc0[1] * yr[2*q + 1] / g_gamma[2*q + 1];
        part += acc1[0] * yr[8 + 2*q] / g_gamma[8 + 2*q];
        part += acc1[1] * yr[9 + 2*q] / g_gamma[9 + 2*q];
    }
    if (rBi < NN) {
        const float* yr = Y + (size_t)rBi * KK;
        part += acc0[2] * yr[2*q]     / g_gamma[2*q];
        part += acc0[3] * yr[2*q + 1] / g_gamma[2*q + 1];
        part += acc1[2] * yr[8 + 2*q] / g_gamma[8 + 2*q];
        part += acc1[3] * yr[9 + 2*q] / g_gamma[9 + 2*q];
    }
#pragma unroll
    for (int o = 16; o; o >>= 1) part += __shfl_xor_sync(0xffffffffu, part, o);

    if (tid == 0) s_red = 0.f;
    __syncthreads();
    if (lane == 0) atomicAdd(&s_red, part);
    __syncthreads();
    if (tid == 0) atomicAdd(&g_result, s_red);
}

// ---------------------------------------------------------------- final
__global__ void k_final(float* out) {
    int t = threadIdx.x;
    float v = 0.f;
    if (t < KK) { float c = g_colsum[t] - MEAN_NODES; v = c * c; }
#pragma unroll
    for (int o = 16; o; o >>= 1) v += __shfl_xor_sync(0xffffffffu, v, o);
    if (t == 0) out[0] = g_result + v;
}

// ---------------------------------------------------------------- launcher
extern "C" void kernel_launch(void* const* d_in, const int* in_sizes, int n_in,
                              void* d_out, int out_size) {
    const float* Y = nullptr;
    const float* A = nullptr;
    const float* deg = nullptr;
    for (int i = 0; i < n_in; i++) {
        if (in_sizes[i] == NN * NN)       A = (const float*)d_in[i];
        else if (in_sizes[i] == NN * KK)  Y = (const float*)d_in[i];
        else if (in_sizes[i] == NN)       deg = (const float*)d_in[i];
    }
    if (!Y)   Y = (const float*)d_in[0];
    if (!A)   A = (const float*)d_in[1];
    if (!deg) deg = (const float*)d_in[2];

    const int SMEM_DYN = DEPTH * SLOT_BYTES;   // 110592
    cudaFuncSetAttribute(k_main, cudaFuncAttributeMaxDynamicSharedMemorySize, SMEM_DYN);

    k_zero<<<1, 64>>>();
    k_gamma<<<40, 256>>>(Y, deg);
    k_bt<<<40, 256>>>(Y);
    dim3 grid(NIT, NJG);
    k_main<<<grid, 256, SMEM_DYN>>>(A, Y);
    k_final<<<1, 32>>>((float*)d_out);
}

// round 4
// speedup vs baseline: 1.7256x; 1.2087x over previous
#include <cuda_runtime.h>
#include <cstdint>

#define NN 10000
#define KK 16
#define MT 128              // i rows per i-tile (8 warps x 16)
#define JC 64               // j per stage
#define JSTG 157            // ceil(10000/64) j-stages per i-tile
#define NIT 79              // ceil(10000/128) i-tiles
#define TOTAL (NIT * JSTG)  // 12403 stages
#define NCTA 296            // 2 per SM, single wave
#define RBASE 41            // TOTAL / NCTA
#define RREM 267            // TOTAL % NCTA
#define DEPTH 3
#define BT_LD 10048         // padded (1-Y)^T leading dim (157*64 = 10048)
#define SLOT_BYTES 36864    // 32KB A + 4KB B
#define NPB 40              // prep blocks
#define MEAN_NODES 625.0f

__device__ float g_partg[NPB * KK];
__device__ float g_partc[NPB * KK];
__device__ float g_invg[KK];
__device__ float g_colsum[KK];
__device__ float g_result;
__device__ float g_bt[KK * BT_LD];   // (1-Y)^T, k-major, zero padded beyond j=NN

// ---------------------------------------------------------------- helpers
__device__ __forceinline__ void cp16(unsigned dst, const void* src) {
    asm volatile("cp.async.cg.shared.global [%0], [%1], 16;" :: "r"(dst), "l"(src) : "memory");
}
__device__ __forceinline__ void zero16(unsigned dst) {
    asm volatile("st.shared.v4.b32 [%0], {%1,%1,%1,%1};" :: "r"(dst), "r"(0) : "memory");
}
__device__ __forceinline__ void ldsm4(uint32_t& r0, uint32_t& r1, uint32_t& r2, uint32_t& r3,
                                      unsigned addr) {
    asm volatile("ldmatrix.sync.aligned.m8n8.x4.shared.b16 {%0,%1,%2,%3}, [%4];"
                 : "=r"(r0), "=r"(r1), "=r"(r2), "=r"(r3) : "r"(addr));
}
__device__ __forceinline__ void mma_tf32(float* d, const uint32_t* a, uint32_t b0, uint32_t b1) {
    asm volatile(
        "mma.sync.aligned.m16n8k8.row.col.f32.tf32.tf32.f32 "
        "{%0,%1,%2,%3}, {%4,%5,%6,%7}, {%8,%9}, {%0,%1,%2,%3};"
        : "+f"(d[0]), "+f"(d[1]), "+f"(d[2]), "+f"(d[3])
        : "r"(a[0]), "r"(a[1]), "r"(a[2]), "r"(a[3]), "r"(b0), "r"(b1));
}

// ---------------------------------------------------------------- prep kernels
// per-block partial gamma/colsum; block 0 thread 0 zeroes g_result
__global__ void k_gamma(const float* __restrict__ Y, const float* __restrict__ deg) {
    int i = blockIdx.x * blockDim.x + threadIdx.x;
    if (blockIdx.x == 0 && threadIdx.x == 0) g_result = 0.f;
    float y[KK];
    float d = 0.f;
    if (i < NN) {
        d = deg[i];
        const float4* y4 = (const float4*)(Y + (size_t)i * KK);
#pragma unroll
        for (int q = 0; q < 4; q++) {
            float4 v = y4[q];
            y[4*q+0] = v.x; y[4*q+1] = v.y; y[4*q+2] = v.z; y[4*q+3] = v.w;
        }
    } else {
#pragma unroll
        for (int k = 0; k < KK; k++) y[k] = 0.f;
    }
    __shared__ float sg[KK], sc[KK];
    if (threadIdx.x < KK) { sg[threadIdx.x] = 0.f; sc[threadIdx.x] = 0.f; }
    __syncthreads();
#pragma unroll
    for (int k = 0; k < KK; k++) {
        float gv = y[k] * d, cv = y[k];
#pragma unroll
        for (int o = 16; o; o >>= 1) {
            gv += __shfl_xor_sync(0xffffffffu, gv, o);
            cv += __shfl_xor_sync(0xffffffffu, cv, o);
        }
        if ((threadIdx.x & 31) == 0) { atomicAdd(&sg[k], gv); atomicAdd(&sc[k], cv); }
    }
    __syncthreads();
    if (threadIdx.x < KK) {
        g_partg[blockIdx.x * KK + threadIdx.x] = sg[threadIdx.x];
        g_partc[blockIdx.x * KK + threadIdx.x] = sc[threadIdx.x];
    }
}

// transpose (1-Y) into padded scratch; block 0 reduces gamma partials -> inv gamma
__global__ void k_bt(const float* __restrict__ Y) {
    if (blockIdx.x == 0 && threadIdx.x < KK) {
        float g = 0.f, c = 0.f;
#pragma unroll 8
        for (int b = 0; b < NPB; b++) {
            g += g_partg[b * KK + threadIdx.x];
            c += g_partc[b * KK + threadIdx.x];
        }
        g_invg[threadIdx.x] = 1.0f / g;
        g_colsum[threadIdx.x] = c;
    }
    int j = blockIdx.x * blockDim.x + threadIdx.x;
    if (j >= BT_LD) return;
    if (j < NN) {
        const float4* y4 = (const float4*)(Y + (size_t)j * KK);
#pragma unroll
        for (int q = 0; q < 4; q++) {
            float4 v = y4[q];
            g_bt[(4*q+0) * BT_LD + j] = 1.0f - v.x;
            g_bt[(4*q+1) * BT_LD + j] = 1.0f - v.y;
            g_bt[(4*q+2) * BT_LD + j] = 1.0f - v.z;
            g_bt[(4*q+3) * BT_LD + j] = 1.0f - v.w;
        }
    } else {
#pragma unroll
        for (int k = 0; k < KK; k++) g_bt[k * BT_LD + j] = 0.f;
    }
}

// ---------------------------------------------------------------- main (persistent)
extern __shared__ char dsm[];

__global__ void __launch_bounds__(256, 2) k_main(const float* __restrict__ A,
                                                 const float* __restrict__ Y) {
    const int tid  = threadIdx.x;
    const int w    = tid >> 5;
    const int lane = tid & 31;
    const unsigned smBase = (unsigned)__cvta_generic_to_shared(dsm);

    // balanced contiguous run of stages
    const int bid  = blockIdx.x;
    const int sid0 = bid * RBASE + (bid < RREM ? bid : RREM);
    const int len  = RBASE + (bid < RREM ? 1 : 0);

    // ---- per-thread ldmatrix source geometry (validated in R3) ----
    const int m    = lane >> 3;
    const int rsub = lane & 7;
    const int rA   = w * 16 + ((m & 1) << 3) + rsub;
    const int pA   = m >> 1;
    const unsigned aOffBase = (unsigned)(rA * 256);
    const unsigned aXor     = (unsigned)((rA & 7) * 16);
    const int rB   = ((m >> 1) << 3) + rsub;
    const int pB   = m & 1;
    const unsigned bOffBase = 32768u + (unsigned)(rB * 256);
    const unsigned bXor     = (unsigned)((rB & 7) * 16);

    float acc0[4] = {0.f, 0.f, 0.f, 0.f};
    float acc1[4] = {0.f, 0.f, 0.f, 0.f};

    // stage filler: t = local index within run (slot = t % DEPTH)
    auto fill = [&](int t) {
        const int sid = sid0 + t;
        const int it  = sid / JSTG;
        const int js  = sid - it * JSTG;
        const int i0  = it * MT;
        const int j0  = js * JC;
        const unsigned sm = smBase + (unsigned)((t % DEPTH) * SLOT_BYTES);
        // A: 128 rows x 16 chunks of 16B
#pragma unroll
        for (int c = tid; c < 2048; c += 256) {
            int r = c >> 4, u = c & 15;
            unsigned dst = sm + (unsigned)(r * 256) + (unsigned)((u ^ (r & 7)) * 16);
            int i = i0 + r;
            int jc = j0 + u * 4;
            if (i < NN && jc < NN)
                cp16(dst, (const char*)(A + (size_t)i * NN + jc));
            else
                zero16(dst);
        }
        // B: 16 rows x 16 chunks = 256, one per thread (padded scratch always valid)
        {
            int r = tid >> 4, u = tid & 15;
            unsigned dst = sm + 32768u + (unsigned)(r * 256) + (unsigned)((u ^ (r & 7)) * 16);
            cp16(dst, (const char*)(g_bt + (size_t)r * BT_LD + j0 + u * 4));
        }
        asm volatile("cp.async.commit_group;" ::: "memory");
    };

    // prologue
#pragma unroll
    for (int t = 0; t < DEPTH; t++) {
        if (t < len) fill(t);
        else asm volatile("cp.async.commit_group;" ::: "memory");
    }

    for (int t = 0; t < len; t++) {
        asm volatile("cp.async.wait_group %0;" :: "n"(DEPTH - 1) : "memory");
        __syncthreads();

        const unsigned sm = smBase + (unsigned)((t % DEPTH) * SLOT_BYTES);
#pragma unroll
        for (int kk = 0; kk < 8; kk++) {
            uint32_t a[4], b[4];
            unsigned aAddr = sm + aOffBase + ((unsigned)((2 * kk + pA) * 16) ^ aXor);
            unsigned bAddr = sm + bOffBase + ((unsigned)((2 * kk + pB) * 16) ^ bXor);
            ldsm4(a[0], a[1], a[2], a[3], aAddr);
            ldsm4(b[0], b[1], b[2], b[3], bAddr);
            mma_tf32(acc0, a, b[0], b[1]);
            mma_tf32(acc1, a, b[2], b[3]);
        }
        __syncthreads();

        if (t + DEPTH < len) fill(t + DEPTH);
        else asm volatile("cp.async.commit_group;" ::: "memory");

        // flush at i-tile boundary or end of run (uniform across CTA)
        const int sid = sid0 + t;
        const int it  = sid / JSTG;
        const int js  = sid - it * JSTG;
        if (js == JSTG - 1 || t == len - 1) {
            const int i0 = it * MT;
            const int q  = lane & 3;
            const int rAi = i0 + w * 16 + (lane >> 2);
            const int rBi = rAi + 8;
            float part = 0.f;
            if (rAi < NN) {
                const float* yr = Y + (size_t)rAi * KK;
                part += acc0[0] * yr[2*q]     * g_invg[2*q];
                part += acc0[1] * yr[2*q + 1] * g_invg[2*q + 1];
                part += acc1[0] * yr[8 + 2*q] * g_invg[8 + 2*q];
                part += acc1[1] * yr[9 + 2*q] * g_invg[9 + 2*q];
            }
            if (rBi < NN) {
                const float* yr = Y + (size_t)rBi * KK;
                part += acc0[2] * yr[2*q]     * g_invg[2*q];
                part += acc0[3] * yr[2*q + 1] * g_invg[2*q + 1];
                part += acc1[2] * yr[8 + 2*q] * g_invg[8 + 2*q];
                part += acc1[3] * yr[9 + 2*q] * g_invg[9 + 2*q];
            }
#pragma unroll
            for (int o = 16; o; o >>= 1) part += __shfl_xor_sync(0xffffffffu, part, o);
            if (lane == 0) atomicAdd(&g_result, part);
#pragma unroll
            for (int z = 0; z < 4; z++) { acc0[z] = 0.f; acc1[z] = 0.f; }
        }
    }
}

// ---------------------------------------------------------------- final
__global__ void k_final(float* out) {
    int t = threadIdx.x;
    float v = 0.f;
    if (t < KK) { float c = g_colsum[t] - MEAN_NODES; v = c * c; }
#pragma unroll
    for (int o = 16; o; o >>= 1) v += __shfl_xor_sync(0xffffffffu, v, o);
    if (t == 0) out[0] = g_result + v;
}

// ---------------------------------------------------------------- launcher
extern "C" void kernel_launch(void* const* d_in, const int* in_sizes, int n_in,
                              void* d_out, int out_size) {
    const float* Y = nullptr;
    const float* A = nullptr;
    const float* deg = nullptr;
    for (int i = 0; i < n_in; i++) {
        if (in_sizes[i] == NN * NN)       A = (const float*)d_in[i];
        else if (in_sizes[i] == NN * KK)  Y = (const float*)d_in[i];
        else if (in_sizes[i] == NN)       deg = (const float*)d_in[i];
    }
    if (!Y)   Y = (const float*)d_in[0];
    if (!A)   A = (const float*)d_in[1];
    if (!deg) deg = (const float*)d_in[2];

    const int SMEM_DYN = DEPTH * SLOT_BYTES;   // 110592
    cudaFuncSetAttribute(k_main, cudaFuncAttributeMaxDynamicSharedMemorySize, SMEM_DYN);

    k_gamma<<<NPB, 256>>>(Y, deg);
    k_bt<<<NPB, 256>>>(Y);
    k_main<<<NCTA, 256, SMEM_DYN>>>(A, Y);
    k_final<<<1, 32>>>((float*)d_out);
}

// round 5
// speedup vs baseline: 1.7362x; 1.0062x over previous
#include <cuda_runtime.h>
#include <cstdint>

#define NN 10000
#define KK 16
#define MT 128              // i rows per i-tile (8 warps x 16)
#define JC 64               // j per stage
#define JSTG 157            // ceil(10000/64) j-stages per i-tile
#define NIT 79              // ceil(10000/128) i-tiles
#define TOTAL (NIT * JSTG)  // 12403 stages
#define NCTA 296            // 2 per SM, single wave
#define RBASE 41            // TOTAL / NCTA
#define RREM 267            // TOTAL % NCTA
#define DEPTH 3
#define BT_LD 10048         // padded (1-Y)^T leading dim (157*64 = 10048)
#define SLOT_BYTES 36864    // 32KB A + 4KB B
#define NPB 40              // prep blocks
#define MEAN_NODES 625.0f

__device__ float g_partg[NPB * KK];
__device__ float g_partc[NPB * KK];
__device__ float g_result;
__device__ unsigned g_done;          // zero-initialized; self-resetting ticket
__device__ float g_bt[KK * BT_LD];   // (1-Y)^T, k-major, zero padded beyond j=NN

// ---------------------------------------------------------------- helpers
__device__ __forceinline__ void cp16(unsigned dst, const void* src) {
    asm volatile("cp.async.cg.shared.global [%0], [%1], 16;" :: "r"(dst), "l"(src) : "memory");
}
__device__ __forceinline__ void zero16(unsigned dst) {
    asm volatile("st.shared.v4.b32 [%0], {%1,%1,%1,%1};" :: "r"(dst), "r"(0) : "memory");
}
__device__ __forceinline__ void ldsm4(uint32_t& r0, uint32_t& r1, uint32_t& r2, uint32_t& r3,
                                      unsigned addr) {
    asm volatile("ldmatrix.sync.aligned.m8n8.x4.shared.b16 {%0,%1,%2,%3}, [%4];"
                 : "=r"(r0), "=r"(r1), "=r"(r2), "=r"(r3) : "r"(addr));
}
__device__ __forceinline__ void mma_tf32(float* d, const uint32_t* a, uint32_t b0, uint32_t b1) {
    asm volatile(
        "mma.sync.aligned.m16n8k8.row.col.f32.tf32.tf32.f32 "
        "{%0,%1,%2,%3}, {%4,%5,%6,%7}, {%8,%9}, {%0,%1,%2,%3};"
        : "+f"(d[0]), "+f"(d[1]), "+f"(d[2]), "+f"(d[3])
        : "r"(a[0]), "r"(a[1]), "r"(a[2]), "r"(a[3]), "r"(b0), "r"(b1));
}

// ---------------------------------------------------------------- fused prep
// One pass over Y: per-block gamma/colsum partials + (1-Y)^T transpose.
__global__ void k_prep(const float* __restrict__ Y, const float* __restrict__ deg) {
    const int t = threadIdx.x;
    const int j = blockIdx.x * 256 + t;
    if (blockIdx.x == 0 && t == 0) g_result = 0.f;

    float y[KK];
    float d = 0.f;
    const bool v = (j < NN);
    if (v) {
        d = deg[j];
        const float4* y4 = (const float4*)(Y + (size_t)j * KK);
#pragma unroll
        for (int q = 0; q < 4; q++) {
            float4 vv = y4[q];
            y[4*q+0] = vv.x; y[4*q+1] = vv.y; y[4*q+2] = vv.z; y[4*q+3] = vv.w;
        }
    } else {
#pragma unroll
        for (int k = 0; k < KK; k++) y[k] = 0.f;
    }

    // transpose (coalesced per k: warp-contiguous j)
    if (j < BT_LD) {
#pragma unroll
        for (int k = 0; k < KK; k++)
            g_bt[(size_t)k * BT_LD + j] = v ? (1.0f - y[k]) : 0.f;
    }

    // block-level partial gamma / colsum
    __shared__ float sg[KK], sc[KK];
    if (t < KK) { sg[t] = 0.f; sc[t] = 0.f; }
    __syncthreads();
#pragma unroll
    for (int k = 0; k < KK; k++) {
        float gv = y[k] * d, cv = y[k];
#pragma unroll
        for (int o = 16; o; o >>= 1) {
            gv += __shfl_xor_sync(0xffffffffu, gv, o);
            cv += __shfl_xor_sync(0xffffffffu, cv, o);
        }
        if ((t & 31) == 0) { atomicAdd(&sg[k], gv); atomicAdd(&sc[k], cv); }
    }
    __syncthreads();
    if (t < KK) {
        g_partg[blockIdx.x * KK + t] = sg[t];
        g_partc[blockIdx.x * KK + t] = sc[t];
    }
}

// ---------------------------------------------------------------- main (persistent)
extern __shared__ char dsm[];

__global__ void __launch_bounds__(256, 2) k_main(const float* __restrict__ A,
                                                 const float* __restrict__ Y,
                                                 float* __restrict__ out) {
    __shared__ float s_invg[KK];

    const int tid  = threadIdx.x;
    const int w    = tid >> 5;
    const int lane = tid & 31;
    const unsigned smBase = (unsigned)__cvta_generic_to_shared(dsm);

    // local inverse-gamma from prep partials (visible after first in-loop syncthreads)
    if (tid < KK) {
        float g = 0.f;
#pragma unroll 8
        for (int b = 0; b < NPB; b++) g += g_partg[b * KK + tid];
        s_invg[tid] = 1.0f / g;
    }

    // balanced contiguous run of stages
    const int bid  = blockIdx.x;
    const int sid0 = bid * RBASE + (bid < RREM ? bid : RREM);
    const int len  = RBASE + (bid < RREM ? 1 : 0);

    // ---- per-thread ldmatrix source geometry (validated R3/R4) ----
    const int m    = lane >> 3;
    const int rsub = lane & 7;
    const int rA   = w * 16 + ((m & 1) << 3) + rsub;
    const int pA   = m >> 1;
    const unsigned aOffBase = (unsigned)(rA * 256);
    const unsigned aXor     = (unsigned)((rA & 7) * 16);
    const int rB   = ((m >> 1) << 3) + rsub;
    const int pB   = m & 1;
    const unsigned bOffBase = 32768u + (unsigned)(rB * 256);
    const unsigned bXor     = (unsigned)((rB & 7) * 16);

    float acc0[4] = {0.f, 0.f, 0.f, 0.f};
    float acc1[4] = {0.f, 0.f, 0.f, 0.f};

    auto fill = [&](int t) {
        const int sid = sid0 + t;
        const int it  = sid / JSTG;
        const int js  = sid - it * JSTG;
        const int i0  = it * MT;
        const int j0  = js * JC;
        const unsigned sm = smBase + (unsigned)((t % DEPTH) * SLOT_BYTES);
#pragma unroll
        for (int c = tid; c < 2048; c += 256) {
            int r = c >> 4, u = c & 15;
            unsigned dst = sm + (unsigned)(r * 256) + (unsigned)((u ^ (r & 7)) * 16);
            int i = i0 + r;
            int jc = j0 + u * 4;
            if (i < NN && jc < NN)
                cp16(dst, (const char*)(A + (size_t)i * NN + jc));
            else
                zero16(dst);
        }
        {
            int r = tid >> 4, u = tid & 15;
            unsigned dst = sm + 32768u + (unsigned)(r * 256) + (unsigned)((u ^ (r & 7)) * 16);
            cp16(dst, (const char*)(g_bt + (size_t)r * BT_LD + j0 + u * 4));
        }
        asm volatile("cp.async.commit_group;" ::: "memory");
    };

#pragma unroll
    for (int t = 0; t < DEPTH; t++) {
        if (t < len) fill(t);
        else asm volatile("cp.async.commit_group;" ::: "memory");
    }

    for (int t = 0; t < len; t++) {
        asm volatile("cp.async.wait_group %0;" :: "n"(DEPTH - 1) : "memory");
        __syncthreads();

        const unsigned sm = smBase + (unsigned)((t % DEPTH) * SLOT_BYTES);
#pragma unroll
        for (int kk = 0; kk < 8; kk++) {
            uint32_t a[4], b[4];
            unsigned aAddr = sm + aOffBase + ((unsigned)((2 * kk + pA) * 16) ^ aXor);
            unsigned bAddr = sm + bOffBase + ((unsigned)((2 * kk + pB) * 16) ^ bXor);
            ldsm4(a[0], a[1], a[2], a[3], aAddr);
            ldsm4(b[0], b[1], b[2], b[3], bAddr);
            mma_tf32(acc0, a, b[0], b[1]);
            mma_tf32(acc1, a, b[2], b[3]);
        }
        __syncthreads();

        if (t + DEPTH < len) fill(t + DEPTH);
        else asm volatile("cp.async.commit_group;" ::: "memory");

        const int sid = sid0 + t;
        const int it  = sid / JSTG;
        const int js  = sid - it * JSTG;
        if (js == JSTG - 1 || t == len - 1) {
            const int i0 = it * MT;
            const int q  = lane & 3;
            const int rAi = i0 + w * 16 + (lane >> 2);
            const int rBi = rAi + 8;
            float part = 0.f;
            if (rAi < NN) {
                const float* yr = Y + (size_t)rAi * KK;
                part += acc0[0] * yr[2*q]     * s_invg[2*q];
                part += acc0[1] * yr[2*q + 1] * s_invg[2*q + 1];
                part += acc1[0] * yr[8 + 2*q] * s_invg[8 + 2*q];
                part += acc1[1] * yr[9 + 2*q] * s_invg[9 + 2*q];
            }
            if (rBi < NN) {
                const float* yr = Y + (size_t)rBi * KK;
                part += acc0[2] * yr[2*q]     * s_invg[2*q];
                part += acc0[3] * yr[2*q + 1] * s_invg[2*q + 1];
                part += acc1[2] * yr[8 + 2*q] * s_invg[8 + 2*q];
                part += acc1[3] * yr[9 + 2*q] * s_invg[9 + 2*q];
            }
#pragma unroll
            for (int o = 16; o; o >>= 1) part += __shfl_xor_sync(0xffffffffu, part, o);
            if (lane == 0) atomicAdd(&g_result, part);
#pragma unroll
            for (int z = 0; z < 4; z++) { acc0[z] = 0.f; acc1[z] = 0.f; }
        }
    }

    // ---- finalization: warp 0 computes error_partition (redundantly, cheap),
    //      the last CTA to arrive writes the output. Safe: one resident wave.
    if (w == 0) {
        float ep = 0.f;
        if (lane < KK) {
            float c = 0.f;
#pragma unroll 8
            for (int b = 0; b < NPB; b++) c += g_partc[b * KK + lane];
            c -= MEAN_NODES;
            ep = c * c;
        }
#pragma unroll
        for (int o = 16; o; o >>= 1) ep += __shfl_xor_sync(0xffffffffu, ep, o);

        if (lane == 0) {
            __threadfence();
            unsigned prev = atomicAdd(&g_done, 1u);
            if (prev == NCTA - 1) {
                g_done = 0;   // reset for graph replay
                float ec = atomicAdd(&g_result, 0.0f);  // coherent read
                out[0] = ec + ep;
            }
        }
    }
}

// ---------------------------------------------------------------- launcher
extern "C" void kernel_launch(void* const* d_in, const int* in_sizes, int n_in,
                              void* d_out, int out_size) {
    const float* Y = nullptr;
    const float* A = nullptr;
    const float* deg = nullptr;
    for (int i = 0; i < n_in; i++) {
        if (in_sizes[i] == NN * NN)       A = (const float*)d_in[i];
        else if (in_sizes[i] == NN * KK)  Y = (const float*)d_in[i];
        else if (in_sizes[i] == NN)       deg = (const float*)d_in[i];
    }
    if (!Y)   Y = (const float*)d_in[0];
    if (!A)   A = (const float*)d_in[1];
    if (!deg) deg = (const float*)d_in[2];

    const int SMEM_DYN = DEPTH * SLOT_BYTES;   // 110592
    cudaFuncSetAttribute(k_main, cudaFuncAttributeMaxDynamicSharedMemorySize, SMEM_DYN);

    k_prep<<<NPB, 256>>>(Y, deg);
    k_main<<<NCTA, 256, SMEM_DYN>>>(A, Y, (float*)d_out);
}

// round 6
// speedup vs baseline: 1.7712x; 1.0201x over previous
#include <cuda_runtime.h>
#include <cstdint>

#define NN 10000
#define KK 16
#define MT 128              // i rows per i-tile (8 warps x 16)
#define JC 64               // j per stage
#define JSTG 157            // ceil(10000/64) j-stages per i-tile
#define NIT 79              // ceil(10000/128) i-tiles
#define TOTAL (NIT * JSTG)  // 12403 stages
#define NCTA 296            // 2 per SM, single wave
#define RBASE 41            // TOTAL / NCTA
#define RREM 267            // TOTAL % NCTA
#define DEPTH 3
#define BT_LD 10048         // padded (1-Y)^T leading dim (157*64 = 10048)
#define SLOT_BYTES 36864    // 32KB A + 4KB B
#define NPB 40              // prep blocks
#define MEAN_NODES 625.0f

__device__ float g_partg[NPB * KK];
__device__ float g_partc[NPB * KK];
__device__ float g_result;
__device__ unsigned g_done;          // zero-initialized; self-resetting ticket
__device__ float g_bt[KK * BT_LD];   // (1-Y)^T, k-major, zero padded beyond j=NN

// ---------------------------------------------------------------- helpers
__device__ __forceinline__ void cp16(unsigned dst, const void* src) {
    asm volatile("cp.async.cg.shared.global [%0], [%1], 16;" :: "r"(dst), "l"(src) : "memory");
}
__device__ __forceinline__ void zero16(unsigned dst) {
    asm volatile("st.shared.v4.b32 [%0], {%1,%1,%1,%1};" :: "r"(dst), "r"(0) : "memory");
}
__device__ __forceinline__ void ldsm4(uint32_t& r0, uint32_t& r1, uint32_t& r2, uint32_t& r3,
                                      unsigned addr) {
    asm volatile("ldmatrix.sync.aligned.m8n8.x4.shared.b16 {%0,%1,%2,%3}, [%4];"
                 : "=r"(r0), "=r"(r1), "=r"(r2), "=r"(r3) : "r"(addr));
}
__device__ __forceinline__ void mma_tf32(float* d, const uint32_t* a, uint32_t b0, uint32_t b1) {
    asm volatile(
        "mma.sync.aligned.m16n8k8.row.col.f32.tf32.tf32.f32 "
        "{%0,%1,%2,%3}, {%4,%5,%6,%7}, {%8,%9}, {%0,%1,%2,%3};"
        : "+f"(d[0]), "+f"(d[1]), "+f"(d[2]), "+f"(d[3])
        : "r"(a[0]), "r"(a[1]), "r"(a[2]), "r"(a[3]), "r"(b0), "r"(b1));
}

// ---------------------------------------------------------------- fused prep
__global__ void k_prep(const float* __restrict__ Y, const float* __restrict__ deg) {
    const int t = threadIdx.x;
    const int j = blockIdx.x * 256 + t;
    if (blockIdx.x == 0 && t == 0) g_result = 0.f;

    float y[KK];
    float d = 0.f;
    const bool v = (j < NN);
    if (v) {
        d = deg[j];
        const float4* y4 = (const float4*)(Y + (size_t)j * KK);
#pragma unroll
        for (int q = 0; q < 4; q++) {
            float4 vv = y4[q];
            y[4*q+0] = vv.x; y[4*q+1] = vv.y; y[4*q+2] = vv.z; y[4*q+3] = vv.w;
        }
    } else {
#pragma unroll
        for (int k = 0; k < KK; k++) y[k] = 0.f;
    }

    if (j < BT_LD) {
#pragma unroll
        for (int k = 0; k < KK; k++)
            g_bt[(size_t)k * BT_LD + j] = v ? (1.0f - y[k]) : 0.f;
    }

    __shared__ float sg[KK], sc[KK];
    if (t < KK) { sg[t] = 0.f; sc[t] = 0.f; }
    __syncthreads();
#pragma unroll
    for (int k = 0; k < KK; k++) {
        float gv = y[k] * d, cv = y[k];
#pragma unroll
        for (int o = 16; o; o >>= 1) {
            gv += __shfl_xor_sync(0xffffffffu, gv, o);
            cv += __shfl_xor_sync(0xffffffffu, cv, o);
        }
        if ((t & 31) == 0) { atomicAdd(&sg[k], gv); atomicAdd(&sc[k], cv); }
    }
    __syncthreads();
    if (t < KK) {
        g_partg[blockIdx.x * KK + t] = sg[t];
        g_partc[blockIdx.x * KK + t] = sc[t];
    }
}

// ---------------------------------------------------------------- main (persistent)
extern __shared__ char dsm[];

__global__ void __launch_bounds__(256, 2) k_main(const float* __restrict__ A,
                                                 const float* __restrict__ Y,
                                                 float* __restrict__ out) {
    __shared__ float s_invg[KK];

    const int tid  = threadIdx.x;
    const int w    = tid >> 5;
    const int lane = tid & 31;
    const unsigned smBase = (unsigned)__cvta_generic_to_shared(dsm);

    if (tid < KK) {
        float g = 0.f;
#pragma unroll 8
        for (int b = 0; b < NPB; b++) g += g_partg[b * KK + tid];
        s_invg[tid] = 1.0f / g;
    }

    const int bid  = blockIdx.x;
    const int sid0 = bid * RBASE + (bid < RREM ? bid : RREM);
    const int len  = RBASE + (bid < RREM ? 1 : 0);

    // ---- per-thread ldmatrix source geometry (validated R3-R5) ----
    const int m    = lane >> 3;
    const int rsub = lane & 7;
    const int rA   = w * 16 + ((m & 1) << 3) + rsub;
    const int pA   = m >> 1;
    const unsigned aOffBase = (unsigned)(rA * 256);
    const unsigned aXor     = (unsigned)((rA & 7) * 16);
    const int rB   = ((m >> 1) << 3) + rsub;
    const int pB   = m & 1;
    const unsigned bOffBase = 32768u + (unsigned)(rB * 256);
    const unsigned bXor     = (unsigned)((rB & 7) * 16);

    float acc0[4] = {0.f, 0.f, 0.f, 0.f};
    float acc1[4] = {0.f, 0.f, 0.f, 0.f};

    auto fill = [&](int t) {
        const int sid = sid0 + t;
        const int it  = sid / JSTG;
        const int js  = sid - it * JSTG;
        const int i0  = it * MT;
        const int j0  = js * JC;
        const unsigned sm = smBase + (unsigned)((t % DEPTH) * SLOT_BYTES);
#pragma unroll
        for (int c = tid; c < 2048; c += 256) {
            int r = c >> 4, u = c & 15;
            unsigned dst = sm + (unsigned)(r * 256) + (unsigned)((u ^ (r & 7)) * 16);
            int i = i0 + r;
            int jc = j0 + u * 4;
            if (i < NN && jc < NN)
                cp16(dst, (const char*)(A + (size_t)i * NN + jc));
            else
                zero16(dst);
        }
        {
            int r = tid >> 4, u = tid & 15;
            unsigned dst = sm + 32768u + (unsigned)(r * 256) + (unsigned)((u ^ (r & 7)) * 16);
            cp16(dst, (const char*)(g_bt + (size_t)r * BT_LD + j0 + u * 4));
        }
        asm volatile("cp.async.commit_group;" ::: "memory");
    };

    // prologue: only DEPTH-1 fills; the loop issues fill(t+2) at its top
    if (0 < len) fill(0); else asm volatile("cp.async.commit_group;" ::: "memory");
    if (1 < len) fill(1); else asm volatile("cp.async.commit_group;" ::: "memory");

    for (int t = 0; t < len; t++) {
        // prefetch FIRST: slot (t+2)%3 == slot (t-1)%3, freed by last iteration's
        // post-compute __syncthreads (WAR safe). DMA overlaps this stage's compute.
        if (t + 2 < len) fill(t + 2);
        else asm volatile("cp.async.commit_group;" ::: "memory");

        asm volatile("cp.async.wait_group %0;" :: "n"(DEPTH - 1) : "memory");
        __syncthreads();

        const unsigned sm = smBase + (unsigned)((t % DEPTH) * SLOT_BYTES);
#pragma unroll
        for (int kk = 0; kk < 8; kk++) {
            uint32_t a[4], b[4];
            unsigned aAddr = sm + aOffBase + ((unsigned)((2 * kk + pA) * 16) ^ aXor);
            unsigned bAddr = sm + bOffBase + ((unsigned)((2 * kk + pB) * 16) ^ bXor);
            ldsm4(a[0], a[1], a[2], a[3], aAddr);
            ldsm4(b[0], b[1], b[2], b[3], bAddr);
            mma_tf32(acc0, a, b[0], b[1]);
            mma_tf32(acc1, a, b[2], b[3]);
        }

        const int sid = sid0 + t;
        const int it  = sid / JSTG;
        const int js  = sid - it * JSTG;
        if (js == JSTG - 1 || t == len - 1) {
            const int i0 = it * MT;
            const int q  = lane & 3;
            const int rAi = i0 + w * 16 + (lane >> 2);
            const int rBi = rAi + 8;
            float part = 0.f;
            if (rAi < NN) {
                const float* yr = Y + (size_t)rAi * KK;
                part += acc0[0] * yr[2*q]     * s_invg[2*q];
                part += acc0[1] * yr[2*q + 1] * s_invg[2*q + 1];
                part += acc1[0] * yr[8 + 2*q] * s_invg[8 + 2*q];
                part += acc1[1] * yr[9 + 2*q] * s_invg[9 + 2*q];
            }
            if (rBi < NN) {
                const float* yr = Y + (size_t)rBi * KK;
                part += acc0[2] * yr[2*q]     * s_invg[2*q];
                part += acc0[3] * yr[2*q + 1] * s_invg[2*q + 1];
                part += acc1[2] * yr[8 + 2*q] * s_invg[8 + 2*q];
                part += acc1[3] * yr[9 + 2*q] * s_invg[9 + 2*q];
            }
#pragma unroll
            for (int o = 16; o; o >>= 1) part += __shfl_xor_sync(0xffffffffu, part, o);
            if (lane == 0) atomicAdd(&g_result, part);
#pragma unroll
            for (int z = 0; z < 4; z++) { acc0[z] = 0.f; acc1[z] = 0.f; }
        }

        __syncthreads();   // all warps done reading slot t -> next iter may refill it
    }

    // ---- finalization: last CTA writes out (single resident wave) ----
    if (w == 0) {
        float ep = 0.f;
        if (lane < KK) {
            float c = 0.f;
#pragma unroll 8
            for (int b = 0; b < NPB; b++) c += g_partc[b * KK + lane];
            c -= MEAN_NODES;
            ep = c * c;
        }
#pragma unroll
        for (int o = 16; o; o >>= 1) ep += __shfl_xor_sync(0xffffffffu, ep, o);

        if (lane == 0) {
            __threadfence();
            unsigned prev = atomicAdd(&g_done, 1u);
            if (prev == NCTA - 1) {
                g_done = 0;   // reset for graph replay
                float ec = atomicAdd(&g_result, 0.0f);  // coherent read
                out[0] = ec + ep;
            }
        }
    }
}

// ---------------------------------------------------------------- launcher
extern "C" void kernel_launch(void* const* d_in, const int* in_sizes, int n_in,
                              void* d_out, int out_size) {
    const float* Y = nullptr;
    const float* A = nullptr;
    const float* deg = nullptr;
    for (int i = 0; i < n_in; i++) {
        if (in_sizes[i] == NN * NN)       A = (const float*)d_in[i];
        else if (in_sizes[i] == NN * KK)  Y = (const float*)d_in[i];
        else if (in_sizes[i] == NN)       deg = (const float*)d_in[i];
    }
    if (!Y)   Y = (const float*)d_in[0];
    if (!A)   A = (const float*)d_in[1];
    if (!deg) deg = (const float*)d_in[2];

    const int SMEM_DYN = DEPTH * SLOT_BYTES;   // 110592
    cudaFuncSetAttribute(k_main, cudaFuncAttributeMaxDynamicSharedMemorySize, SMEM_DYN);

    k_prep<<<NPB, 256>>>(Y, deg);
    k_main<<<NCTA, 256, SMEM_DYN>>>(A, Y, (float*)d_out);
}